// round 12
// baseline (speedup 1.0000x reference)
#include <cuda_runtime.h>
#include <cuda_fp16.h>
#include <cstdint>
#include <math.h>

// ============================================================================
// EdgeModel, persistent warp-specialized fp16 mma.sync kernel (baseline PTX):
//   out[e] = softplus( concat(nf[src], nf[dst], ef[e], gf[batch[src]]) @ W.T ) - log2
// R12 = R9 (passing, 358us) + ONE change: K-chunk order permuted so the ef
// chunk (fp32 LDG+cvt+STS, the only non-cp.async slab) is LAST; producer
// commits+arrives slabs 0-4 (pure cp.async) first so consumers start
// immediately, then converts ef overlapped with consumer compute.
// W image chunk mapping permuted to match: chunks 0-3 nf, chunk 4 gf, chunk 5 ef.
// Statics identical to R9 (~13MB) — the 100MB+ statics of R10/R11 silently
// killed all launches.
// ============================================================================

#define DN 128
#define DE 64
#define DG 64
#define H  128
#define TILE_E 128
#define THREADS 256
#define NSLAB 6
#define SLAB 16384                       // 128 rows x 64 f16 (128B rows)
#define OFF_RING (NSLAB * SLAB)          // 98304
#define OFF_IDX  (OFF_RING + NSLAB * SLAB)   // 196608
#define OFF_MBAR (OFF_IDX + 3 * TILE_E * 4)
#define SMEM_TOTAL (OFF_MBAR + 128)
#define LOG2F_CONST 0.6931471805599453f

#define SWZ128(off) ((off) ^ (((off) >> 3) & 0x70))

#define N_CAP 50000
#define G_CAP 256

// W image: [6 chunks][128 n x 64 k] fp16, SW128-swizzled rows (128B)
// chunk order: 0-1 nf_src, 2-3 nf_dst, 4 gf, 5 ef   (ef LAST)
__device__ uint16_t g_Wimg[NSLAB * 128 * 64];
// fp16 row images (plain row-major): nf [N][128], gf [G][64]
__device__ uint16_t g_nfh[N_CAP * DN];
__device__ uint16_t g_gfh[G_CAP * DG];

__global__ void w_convert_kernel(const float* __restrict__ W) {
    int i = blockIdx.x * 256 + threadIdx.x;      // over 128*384
    if (i >= H * 384) return;
    int n = i / 384, k = i - n * 384;
    // concat layout: [0,256) nf pair, [256,320) ef, [320,384) gf
    int c;
    if (k < 256)      c = k >> 6;   // chunks 0-3
    else if (k < 320) c = 5;        // ef -> chunk 5
    else              c = 4;        // gf -> chunk 4
    int kk = k & 63;
    __half h = __float2half_rn(W[i]);
    *(uint16_t*)((char*)g_Wimg + (size_t)c * SLAB + SWZ128((uint32_t)(n * 128 + kk * 2)))
        = __half_as_ushort(h);
}

__global__ void nf_convert_kernel(const float* __restrict__ nf, int total4) {
    int i = blockIdx.x * 256 + threadIdx.x;      // over N*128/4
    if (i >= total4) return;
    float4 v = ((const float4*)nf)[i];
    __half2 a = __floats2half2_rn(v.x, v.y);
    __half2 b = __floats2half2_rn(v.z, v.w);
    uint2 pk; pk.x = *(uint32_t*)&a; pk.y = *(uint32_t*)&b;
    ((uint2*)g_nfh)[i] = pk;
}

__global__ void gf_convert_kernel(const float* __restrict__ gf, int total4) {
    int i = blockIdx.x * 256 + threadIdx.x;      // over G*64/4
    if (i >= total4) return;
    float4 v = ((const float4*)gf)[i];
    __half2 a = __floats2half2_rn(v.x, v.y);
    __half2 b = __floats2half2_rn(v.z, v.w);
    uint2 pk; pk.x = *(uint32_t*)&a; pk.y = *(uint32_t*)&b;
    ((uint2*)g_gfh)[i] = pk;
}

__device__ __forceinline__ uint32_t smem_u32(const void* p) {
    uint32_t a;
    asm("{ .reg .u64 t; cvta.to.shared.u64 t, %1; cvt.u32.u64 %0, t; }" : "=r"(a) : "l"(p));
    return a;
}
__device__ __forceinline__ void ldsm_x4(uint32_t* r, uint32_t addr) {
    asm volatile("ldmatrix.sync.aligned.m8n8.x4.shared.b16 {%0,%1,%2,%3}, [%4];"
                 : "=r"(r[0]), "=r"(r[1]), "=r"(r[2]), "=r"(r[3]) : "r"(addr));
}
__device__ __forceinline__ void cp_async16(uint32_t dst, const void* src) {
    asm volatile("cp.async.cg.shared.global [%0], [%1], 16;" :: "r"(dst), "l"(src));
}
__device__ __forceinline__ void mma_f16(float* d, const uint32_t* a, uint32_t b0, uint32_t b1) {
    asm volatile(
        "mma.sync.aligned.m16n8k16.row.col.f32.f16.f16.f32 "
        "{%0,%1,%2,%3}, {%4,%5,%6,%7}, {%8,%9}, {%0,%1,%2,%3};"
        : "+f"(d[0]), "+f"(d[1]), "+f"(d[2]), "+f"(d[3])
        : "r"(a[0]), "r"(a[1]), "r"(a[2]), "r"(a[3]), "r"(b0), "r"(b1));
}
__device__ __forceinline__ float softplus_shift(float h) {
    return fmaxf(h, 0.0f) + __logf(1.0f + __expf(-fabsf(h))) - LOG2F_CONST;
}

#define MBAR_INIT(mbar, cnt) \
    asm volatile("mbarrier.init.shared.b64 [%0], %1;" \
        :: "r"((uint32_t)(mbar)), "r"((uint32_t)(cnt)) : "memory")
#define MBAR_ARRIVE(mbar) \
    asm volatile("mbarrier.arrive.shared.b64 _, [%0];" :: "r"((uint32_t)(mbar)) : "memory")
#define MBAR_WAIT(mbar, parity) do { \
    uint32_t _m = (uint32_t)(mbar); uint32_t _p = (uint32_t)(parity); uint32_t _d; \
    asm volatile("{\n\t.reg .pred p;\n\t" \
        "mbarrier.try_wait.parity.acquire.cta.shared::cta.b64 p, [%1], %2;\n\t" \
        "selp.b32 %0, 1, 0, p;\n\t}" : "=r"(_d) : "r"(_m), "r"(_p) : "memory"); \
    if (!_d) { \
        asm volatile("{\n\t.reg .pred P1;\n\tWL_%=:\n\t" \
            "mbarrier.try_wait.parity.acquire.cta.shared::cta.b64 P1, [%0], %1, 0x989680;\n\t" \
            "@P1 bra.uni WD_%=;\n\tbra.uni WL_%=;\n\tWD_%=:\n\t}" \
            :: "r"(_m), "r"(_p) : "memory"); \
    } } while (0)

__global__ __launch_bounds__(THREADS, 1)
void edge_ws_kernel(const float* __restrict__ ef,
                    const int*   __restrict__ ei,
                    const int*   __restrict__ batch,
                    float*       __restrict__ out,
                    int E, int ntiles)
{
    extern __shared__ __align__(1024) char smem[];
    const uint32_t sbase = smem_u32(smem);
    const int tid  = threadIdx.x;
    const int wid  = tid >> 5;
    const int lane = tid & 31;

    // ---- one-time: resident W copy (96KB) + mbarrier init ----
    {
        const char* wsrc = (const char*)g_Wimg;
        #pragma unroll
        for (int j = 0; j < 24; ++j)
            cp_async16(sbase + tid * 16 + j * 4096, wsrc + tid * 16 + j * 4096);
        asm volatile("cp.async.commit_group;" ::: "memory");
        asm volatile("cp.async.wait_group 0;" ::: "memory");
    }
    if (tid == 0) {
        #pragma unroll
        for (int s = 0; s < NSLAB; ++s) {
            MBAR_INIT(sbase + OFF_MBAR + s * 8, 128);        // full[s]
            MBAR_INIT(sbase + OFF_MBAR + 48 + s * 8, 128);   // empty[s]
        }
    }
    __syncthreads();   // last block-wide barrier

    if (wid >= 4) {
        // ======================= PRODUCER (warps 4-7) =======================
        const int pw    = wid - 4;
        const int wrow0 = pw * 32;
        int* s_src = (int*)(smem + OFF_IDX);
        int* s_dst = s_src + TILE_E;
        int* s_g   = s_dst + TILE_E;
        const int l8 = lane & 7;       // 16B chunk within row
        const int r4 = lane >> 3;      // row within 4-row group
        int tcnt = 0;
        for (int tile = blockIdx.x; tile < ntiles; tile += gridDim.x, ++tcnt) {
            // stage indices (warp-local rows wrow0..wrow0+31)
            {
                const int e  = tile * TILE_E + wrow0 + lane;
                const int ee = (e < E) ? e : 0;
                const int is = ei[ee];
                s_src[wrow0 + lane] = is;
                s_dst[wrow0 + lane] = ei[E + ee];
                s_g[wrow0 + lane]   = batch[is];
            }
            __syncwarp();

            const uint32_t ew_par = (tcnt & 1) ^ 1;
            const uint32_t ring   = sbase + OFF_RING;

            // ---- slabs 0-4: pure cp.async (nf_src x2, nf_dst x2, gf) ----
            #pragma unroll
            for (int sl = 0; sl < 5; ++sl) {
                if (tcnt > 0) MBAR_WAIT(sbase + OFF_MBAR + 48 + sl * 8, ew_par);
                #pragma unroll
                for (int g = 0; g < 8; ++g) {
                    const int r = wrow0 + g * 4 + r4;
                    const char* src;
                    if (sl < 2)      src = (const char*)g_nfh + (size_t)s_src[r] * 256 + sl * 128;
                    else if (sl < 4) src = (const char*)g_nfh + (size_t)s_dst[r] * 256 + (sl - 2) * 128;
                    else             src = (const char*)g_gfh + (size_t)s_g[r] * 128;
                    cp_async16(ring + sl * SLAB + SWZ128((uint32_t)(r * 128 + l8 * 16)),
                               src + l8 * 16);
                }
                asm volatile("cp.async.commit_group;" ::: "memory");
            }
            // ---- drain + arrive fulls 0-4 (consumer starts immediately) ----
            asm volatile("cp.async.wait_group 4;" ::: "memory");
            MBAR_ARRIVE(sbase + OFF_MBAR + 0 * 8);
            asm volatile("cp.async.wait_group 3;" ::: "memory");
            MBAR_ARRIVE(sbase + OFF_MBAR + 1 * 8);
            asm volatile("cp.async.wait_group 2;" ::: "memory");
            MBAR_ARRIVE(sbase + OFF_MBAR + 2 * 8);
            asm volatile("cp.async.wait_group 1;" ::: "memory");
            MBAR_ARRIVE(sbase + OFF_MBAR + 3 * 8);
            asm volatile("cp.async.wait_group 0;" ::: "memory");
            MBAR_ARRIVE(sbase + OFF_MBAR + 4 * 8);

            // ---- slab 5: ef fp32 LDG+cvt+STS, overlapped with consumer ----
            if (tcnt > 0) MBAR_WAIT(sbase + OFF_MBAR + 48 + 5 * 8, ew_par);
            {
                char* dst = smem + OFF_RING + 5 * SLAB;
                #pragma unroll
                for (int g = 0; g < 8; ++g) {
                    const int r  = wrow0 + g * 4 + r4;
                    const int e  = tile * TILE_E + r;
                    const int ee = (e < E) ? e : 0;
                    const float* rp = ef + (size_t)ee * DE;
                    float4 v0 = *(const float4*)(rp + l8 * 4);
                    float4 v1 = *(const float4*)(rp + 32 + l8 * 4);
                    __half2 a0 = __floats2half2_rn(v0.x, v0.y);
                    __half2 b0 = __floats2half2_rn(v0.z, v0.w);
                    __half2 a1 = __floats2half2_rn(v1.x, v1.y);
                    __half2 b1 = __floats2half2_rn(v1.z, v1.w);
                    uint2 p0; p0.x = *(uint32_t*)&a0; p0.y = *(uint32_t*)&b0;
                    uint2 p1; p1.x = *(uint32_t*)&a1; p1.y = *(uint32_t*)&b1;
                    *(uint2*)(dst + SWZ128((uint32_t)(r * 128 + l8 * 8)))      = p0;
                    *(uint2*)(dst + SWZ128((uint32_t)(r * 128 + 64 + l8 * 8))) = p1;
                }
            }
            MBAR_ARRIVE(sbase + OFF_MBAR + 5 * 8);
        }
    } else {
        // ======================= CONSUMER (warps 0-3) =======================
        const int wm = wid & 1;       // rows wm*64
        const int wn = wid >> 1;      // cols wn*64
        int tcnt = 0;
        for (int tile = blockIdx.x; tile < ntiles; tile += gridDim.x, ++tcnt) {
            const int e0 = tile * TILE_E;
            float acc[4][8][4];
            #pragma unroll
            for (int mt = 0; mt < 4; ++mt)
                #pragma unroll
                for (int nt = 0; nt < 8; ++nt)
                    #pragma unroll
                    for (int z = 0; z < 4; ++z) acc[mt][nt][z] = 0.0f;

            const uint32_t fw_par = tcnt & 1;
            #pragma unroll 1
            for (int sl = 0; sl < NSLAB; ++sl) {
                MBAR_WAIT(sbase + OFF_MBAR + sl * 8, fw_par);
                const uint32_t Abase = sbase + OFF_RING + sl * SLAB;
                const uint32_t Bbase = sbase + sl * SLAB;
                #pragma unroll
                for (int ks = 0; ks < 4; ++ks) {
                    uint32_t af[4][4], bf[4][4];
                    {
                        const int rofs = lane & 15;
                        const int cofs = ks * 32 + ((lane >> 4) & 1) * 16;
                        #pragma unroll
                        for (int mt = 0; mt < 4; ++mt) {
                            const int row = wm * 64 + mt * 16 + rofs;
                            ldsm_x4(af[mt], Abase + SWZ128((uint32_t)(row * 128 + cofs)));
                        }
                    }
                    {
                        const int rofs = (lane & 7) + ((lane >> 4) & 1) * 8;
                        const int cofs = ks * 32 + ((lane >> 3) & 1) * 16;
                        #pragma unroll
                        for (int nt = 0; nt < 4; ++nt) {
                            const int row = wn * 64 + nt * 16 + rofs;
                            ldsm_x4(bf[nt], Bbase + SWZ128((uint32_t)(row * 128 + cofs)));
                        }
                    }
                    #pragma unroll
                    for (int mt = 0; mt < 4; ++mt)
                        #pragma unroll
                        for (int nt = 0; nt < 4; ++nt) {
                            mma_f16(acc[mt][2 * nt + 0], af[mt], bf[nt][0], bf[nt][1]);
                            mma_f16(acc[mt][2 * nt + 1], af[mt], bf[nt][2], bf[nt][3]);
                        }
                }
                MBAR_ARRIVE(sbase + OFF_MBAR + 48 + sl * 8);
            }

            // ---- epilogue: softplus + store (overlaps next tile's gather) ----
            #pragma unroll
            for (int mt = 0; mt < 4; ++mt) {
                const int r0 = e0 + wm * 64 + mt * 16 + (lane >> 2);
                const int r1 = r0 + 8;
                #pragma unroll
                for (int nt = 0; nt < 8; ++nt) {
                    const int col = wn * 64 + nt * 8 + (lane & 3) * 2;
                    if (r0 < E) {
                        float2 o;
                        o.x = softplus_shift(acc[mt][nt][0]);
                        o.y = softplus_shift(acc[mt][nt][1]);
                        *(float2*)(out + (size_t)r0 * H + col) = o;
                    }
                    if (r1 < E) {
                        float2 o;
                        o.x = softplus_shift(acc[mt][nt][2]);
                        o.y = softplus_shift(acc[mt][nt][3]);
                        *(float2*)(out + (size_t)r1 * H + col) = o;
                    }
                }
            }
        }
    }
}

extern "C" void kernel_launch(void* const* d_in, const int* in_sizes, int n_in,
                              void* d_out, int out_size)
{
    const float* nf    = (const float*)d_in[0];
    const float* ef    = (const float*)d_in[1];
    const float* gf    = (const float*)d_in[2];
    const int*   ei    = (const int*)d_in[3];
    const int*   batch = (const int*)d_in[4];
    const float* W     = (const float*)d_in[5];
    float*       out   = (float*)d_out;

    const int E = in_sizes[1] / DE;              // edge_feats is [E, 64]
    const int N = in_sizes[0] / DN;
    const int G = in_sizes[2] / DG;
    const int ntiles = (E + TILE_E - 1) / TILE_E;

    static int sms = 0;
    if (sms == 0) {
        cudaDeviceGetAttribute(&sms, cudaDevAttrMultiProcessorCount, 0);
        if (sms <= 0) sms = 148;
        cudaFuncSetAttribute(edge_ws_kernel,
                             cudaFuncAttributeMaxDynamicSharedMemorySize, SMEM_TOTAL);
    }

    w_convert_kernel<<<(H * 384 + 255) / 256, 256>>>(W);
    const int nf4 = N * DN / 4;
    nf_convert_kernel<<<(nf4 + 255) / 256, 256>>>(nf, nf4);
    const int gf4 = G * DG / 4;
    gf_convert_kernel<<<(gf4 + 255) / 256, 256>>>(gf, gf4);
    edge_ws_kernel<<<sms, THREADS, SMEM_TOTAL>>>(ef, ei, batch, out, E, ntiles);
}